// round 15
// baseline (speedup 1.0000x reference)
#include <cuda_runtime.h>
#include <cuda_fp16.h>
#include <math.h>
#include <float.h>
#include <stdint.h>

#define NB    8
#define TLEN  4096
#define BT    (NB * TLEN)   // 32768
#define DM    128
#define HD    64
#define HSK   72            // attn smem stride (halves); conflict-free ldmatrix
#define XSK   136           // qkv X smem stride (halves)
#define WSK   200           // qkv W smem stride (halves)
#define CH    16            // kv tiles per chunk CTA
#define MAXNCH 4            // max chunks per q-tile (64/CH)

// Scratch. Q pre-scaled by 1/sqrt(128)*log2(e). Everything fp16.
__device__ __half g_Xh[BT * DM];        // x converted to fp16
__device__ __half g_Wh[DM * 192];       // fused W fp16 [k][Q|K|V], Wq pre-scaled
__device__ __half g_Qh[BT * HD];
__device__ __half g_Kh[BT * HD];
__device__ __half g_Vh[BT * HD];

// Split-KV partials + completion counters
__device__ float g_Po[NB * 64 * MAXNCH * 64 * 64];   // 33.5 MB
__device__ float g_Pm[NB * 64 * MAXNCH * 64];
__device__ float g_Pl[NB * 64 * MAXNCH * 64];
__device__ int   g_cnt[NB * 64];

// ---------------------------------------------------------------------------
// helpers
// ---------------------------------------------------------------------------
__device__ __forceinline__ float ex2f(float x) {
    float r;
    asm("ex2.approx.ftz.f32 %0, %1;" : "=f"(r) : "f"(x));
    return r;
}
__device__ __forceinline__ uint32_t h2pack(float a, float b) {
    __half2 h = __floats2half2_rn(a, b);
    return *(uint32_t*)&h;
}
__device__ __forceinline__ void mma_f16(float* d, const uint32_t* a,
                                        uint32_t b0, uint32_t b1) {
    asm volatile(
        "mma.sync.aligned.m16n8k16.row.col.f32.f16.f16.f32 "
        "{%0,%1,%2,%3}, {%4,%5,%6,%7}, {%8,%9}, {%0,%1,%2,%3};\n"
        : "+f"(d[0]), "+f"(d[1]), "+f"(d[2]), "+f"(d[3])
        : "r"(a[0]), "r"(a[1]), "r"(a[2]), "r"(a[3]), "r"(b0), "r"(b1));
}
__device__ __forceinline__ void ldm_x4(uint32_t* r, const void* p) {
    uint32_t a = (uint32_t)__cvta_generic_to_shared(p);
    asm volatile("ldmatrix.sync.aligned.m8n8.x4.shared.b16 {%0,%1,%2,%3}, [%4];"
        : "=r"(r[0]), "=r"(r[1]), "=r"(r[2]), "=r"(r[3]) : "r"(a));
}
__device__ __forceinline__ void ldm_x4t(uint32_t* r, const void* p) {
    uint32_t a = (uint32_t)__cvta_generic_to_shared(p);
    asm volatile("ldmatrix.sync.aligned.m8n8.x4.trans.shared.b16 {%0,%1,%2,%3}, [%4];"
        : "=r"(r[0]), "=r"(r[1]), "=r"(r[2]), "=r"(r[3]) : "r"(a));
}
__device__ __forceinline__ void cpa16(void* dst, const void* src) {
    uint32_t d = (uint32_t)__cvta_generic_to_shared(dst);
    asm volatile("cp.async.cg.shared.global [%0], [%1], 16;" :: "r"(d), "l"(src));
}
#define CP_COMMIT() asm volatile("cp.async.commit_group;")
#define CP_WAIT0()  asm volatile("cp.async.wait_group 0;" ::: "memory")

// softmax scale folded into Wq: 1/sqrt(128) * log2(e)
#define QSCL (0.08838834764831845f * 1.4426950408889634f)

// ---------------------------------------------------------------------------
// Streaming conversion: x -> fp16, W -> fused pre-scaled fp16.
// Also zeroes the split-KV completion counters (graph-replay-safe).
// ---------------------------------------------------------------------------
__global__ __launch_bounds__(256) void cvt_kernel(
    const float* __restrict__ x,
    const float* __restrict__ Wq,
    const float* __restrict__ Wk,
    const float* __restrict__ Wv)
{
    const int tid = blockIdx.x * 256 + threadIdx.x;
    if (tid < NB * 64) g_cnt[tid] = 0;

    const int NX4 = BT * DM / 4;
    for (int i = tid; i < NX4; i += (int)gridDim.x * 256) {
        float4 v = *(const float4*)(x + 4 * (size_t)i);
        uint2 h;
        h.x = h2pack(v.x, v.y);
        h.y = h2pack(v.z, v.w);
        *(uint2*)&g_Xh[4 * (size_t)i] = h;
    }
    const int NW4 = DM * 192 / 4;
    for (int i = tid; i < NW4; i += (int)gridDim.x * 256) {
        int k  = (4 * i) / 192;
        int c  = (4 * i) % 192;
        const float* src;
        float sc;
        if (c < 64)       { src = Wq + k * 64 + c;        sc = QSCL; }
        else if (c < 128) { src = Wk + k * 64 + (c - 64); sc = 1.0f; }
        else              { src = Wv + k * 64 + (c - 128); sc = 1.0f; }
        float4 v = *(const float4*)src;
        uint2 h;
        h.x = h2pack(v.x * sc, v.y * sc);
        h.y = h2pack(v.z * sc, v.w * sc);
        *(uint2*)&g_Wh[k * 192 + c] = h;
    }
}

// ---------------------------------------------------------------------------
// QKV projection as an fp16 smem GEMM, cp.async staging only (proven).
// ---------------------------------------------------------------------------
__global__ __launch_bounds__(256) void qkv_kernel()
{
    extern __shared__ __half smh[];
    __half* Xs = smh;               // [128][XSK]
    __half* Ws = smh + 128 * XSK;   // [128][WSK]

    const int tid  = threadIdx.x;
    const int row0 = blockIdx.x * 128;

    #pragma unroll
    for (int idx = tid; idx < 128 * 16; idx += 256) {
        int r = idx >> 4, c8 = (idx & 15) * 8;
        cpa16(&Xs[r * XSK + c8], g_Xh + (size_t)(row0 + r) * DM + c8);
    }
    #pragma unroll
    for (int idx = tid; idx < 128 * 24; idx += 256) {
        int k = idx / 24, c8 = (idx % 24) * 8;
        cpa16(&Ws[k * WSK + c8], g_Wh + k * 192 + c8);
    }
    CP_COMMIT();
    CP_WAIT0();
    __syncthreads();

    const int warp = tid >> 5, lane = tid & 31;
    const int g = lane >> 2, qi = lane & 3;
    const int rowbase = 32 * (warp >> 1);
    const int colbase = 96 * (warp & 1);
    const int arow  = ((lane >> 3) & 1) * 8 + (lane & 7);
    const int acol8 = (lane >> 4) * 8;
    const int wrow  = ((lane >> 3) & 1) * 8 + (lane & 7);
    const int wcol8 = (lane >> 4) * 8;

    float s[2][12][4];
    #pragma unroll
    for (int rg = 0; rg < 2; rg++)
        #pragma unroll
        for (int nt = 0; nt < 12; nt++)
            #pragma unroll
            for (int e = 0; e < 4; e++) s[rg][nt][e] = 0.f;

    #pragma unroll
    for (int ks = 0; ks < 8; ks++) {
        uint32_t qa0[4], qa1[4];
        ldm_x4(qa0, &Xs[(rowbase + arow) * XSK + 16 * ks + acol8]);
        ldm_x4(qa1, &Xs[(rowbase + 16 + arow) * XSK + 16 * ks + acol8]);
        #pragma unroll
        for (int np = 0; np < 6; np++) {
            uint32_t wf[4];
            ldm_x4t(wf, &Ws[(16 * ks + wrow) * WSK + colbase + 16 * np + wcol8]);
            mma_f16(s[0][2 * np],     qa0, wf[0], wf[1]);
            mma_f16(s[1][2 * np],     qa1, wf[0], wf[1]);
            mma_f16(s[0][2 * np + 1], qa0, wf[2], wf[3]);
            mma_f16(s[1][2 * np + 1], qa1, wf[2], wf[3]);
        }
    }

    #pragma unroll
    for (int rg = 0; rg < 2; rg++) {
        #pragma unroll
        for (int nt = 0; nt < 12; nt++) {
            int c0 = colbase + 8 * nt + 2 * qi;
            int rA = row0 + rowbase + 16 * rg + g;
            #pragma unroll
            for (int half = 0; half < 2; half++) {
                int r = rA + 8 * half;
                __half2 hv = __floats2half2_rn(s[rg][nt][2 * half + 0],
                                               s[rg][nt][2 * half + 1]);
                if (c0 < 64) {
                    *(__half2*)&g_Qh[(size_t)r * HD + c0] = hv;
                } else if (c0 < 128) {
                    *(__half2*)&g_Kh[(size_t)r * HD + (c0 - 64)] = hv;
                } else {
                    *(__half2*)&g_Vh[(size_t)r * HD + (c0 - 128)] = hv;
                }
            }
        }
    }
}

// ---------------------------------------------------------------------------
// Causal flash attention, split-KV CH=16 with FUSED last-CTA combine.
// Inner loop identical to R11-R14 (proven). Multi-chunk CTAs write partials,
// threadfence + atomic; the last-arriving CTA per q-tile reduces all chunks
// (fixed chunk order -> deterministic) and writes the output.
// ---------------------------------------------------------------------------
__global__ __launch_bounds__(128, 4) void attn_kernel(float* __restrict__ Out)
{
    extern __shared__ float sm[];
    __half* base = (__half*)sm;
    __half* Kb[2] = { base,                base + 64 * HSK };
    __half* Vh[2] = { base + 2 * 64 * HSK, base + 3 * 64 * HSK };
    __shared__ int s_last;

    // map work unit -> (qb, chunk); biggest chunks scheduled first
    const int wu = 159 - (int)blockIdx.x;
    int gI = 0;
    while (wu >= 8 * (gI + 1) * (gI + 2)) gI++;       // offsets[g] = 8g(g+1)
    const int rem   = wu - 8 * gI * (gI + 1);
    const int qb    = 16 * gI + rem / (gI + 1);
    const int chunk = rem % (gI + 1);
    const int nch   = qb / CH + 1;
    const int t0 = chunk * CH;
    const int t1 = min(t0 + CH, qb + 1);

    const int b    = blockIdx.y;
    const int tid  = threadIdx.x;
    const int warp = tid >> 5, lane = tid & 31;
    const int g    = lane >> 2, qi = lane & 3;

    const int arow  = ((lane >> 3) & 1) * 8 + (lane & 7);
    const int acol8 = (lane >> 4) * 8;
    const int krow  = (lane & 7) + ((lane >> 4) << 3);
    const int kcol8 = ((lane >> 3) & 1) * 8;
    const int vrow  = ((lane >> 3) & 1) * 8 + (lane & 7);
    const int vcol8 = (lane >> 4) * 8;

    const __half* Kg0 = g_Kh + (size_t)b * TLEN * HD;
    const __half* Vg0 = g_Vh + (size_t)b * TLEN * HD;

    // preload K(t0)+V(t0) as one group
    #pragma unroll
    for (int idx = tid; idx < 64 * 8; idx += 128) {
        int r = idx >> 3, c8 = (idx & 7) * 8;
        cpa16(&Kb[0][r * HSK + c8], Kg0 + (size_t)(t0 * 64 + r) * HD + c8);
        cpa16(&Vh[0][r * HSK + c8], Vg0 + (size_t)(t0 * 64 + r) * HD + c8);
    }
    CP_COMMIT();

    // stage Q (fp16, pre-scaled) into Kb[1], pull A-fragments
    const __half* Qg = g_Qh + ((size_t)b * TLEN + (size_t)qb * 64) * HD;
    #pragma unroll
    for (int idx = tid; idx < 64 * 8; idx += 128) {
        int r = idx >> 3, c8 = (idx & 7) * 8;
        *(uint4*)&Kb[1][r * HSK + c8] = *(const uint4*)(Qg + (size_t)r * HD + c8);
    }
    __syncthreads();

    uint32_t qa[4][4];
    #pragma unroll
    for (int ks = 0; ks < 4; ks++)
        ldm_x4(qa[ks], &Kb[1][(16 * warp + arow) * HSK + 16 * ks + acol8]);

    float o[8][4];
    #pragma unroll
    for (int nt = 0; nt < 8; nt++)
        #pragma unroll
        for (int e = 0; e < 4; e++) o[nt][e] = 0.f;
    float m0 = -1e30f, m1 = -1e30f, l0 = 0.f, l1 = 0.f;  // l: lane-partial

    const int qr = 16 * warp + g;

    for (int kb = t0; kb < t1; kb++) {
        const int cur = (kb - t0) & 1;

        CP_WAIT0();
        __syncthreads();

        if (kb + 1 < t1) {
            const __half* Kg = Kg0 + (size_t)(kb + 1) * 64 * HD;
            const __half* Vg = Vg0 + (size_t)(kb + 1) * 64 * HD;
            #pragma unroll
            for (int idx = tid; idx < 64 * 8; idx += 128) {
                int r = idx >> 3, c8 = (idx & 7) * 8;
                cpa16(&Kb[1 - cur][r * HSK + c8], Kg + (size_t)r * HD + c8);
                cpa16(&Vh[1 - cur][r * HSK + c8], Vg + (size_t)r * HD + c8);
            }
        }
        CP_COMMIT();

        // --- S = Q K^T ---
        float s[8][4];
        #pragma unroll
        for (int nt = 0; nt < 8; nt++)
            #pragma unroll
            for (int e = 0; e < 4; e++) s[nt][e] = 0.f;

        #pragma unroll
        for (int ks = 0; ks < 4; ks++) {
            #pragma unroll
            for (int ntp = 0; ntp < 4; ntp++) {
                uint32_t kf[4];
                ldm_x4(kf, &Kb[cur][(16 * ntp + krow) * HSK + 16 * ks + kcol8]);
                mma_f16(s[2 * ntp],     qa[ks], kf[0], kf[1]);
                mma_f16(s[2 * ntp + 1], qa[ks], kf[2], kf[3]);
            }
        }

        // --- causal mask: diagonal tile only ---
        if (kb == qb) {
            #pragma unroll
            for (int nt = 0; nt < 8; nt++) {
                int c0 = 8 * nt + 2 * qi;
                if (c0     > qr    ) s[nt][0] = -1e30f;
                if (c0 + 1 > qr    ) s[nt][1] = -1e30f;
                if (c0     > qr + 8) s[nt][2] = -1e30f;
                if (c0 + 1 > qr + 8) s[nt][3] = -1e30f;
            }
        }

        // --- online softmax (exp2 domain); l lane-partial ---
        float rm0 = -1e30f, rm1 = -1e30f;
        #pragma unroll
        for (int nt = 0; nt < 8; nt++) {
            rm0 = fmaxf(rm0, fmaxf(s[nt][0], s[nt][1]));
            rm1 = fmaxf(rm1, fmaxf(s[nt][2], s[nt][3]));
        }
        rm0 = fmaxf(rm0, __shfl_xor_sync(0xffffffffu, rm0, 1));
        rm0 = fmaxf(rm0, __shfl_xor_sync(0xffffffffu, rm0, 2));
        rm1 = fmaxf(rm1, __shfl_xor_sync(0xffffffffu, rm1, 1));
        rm1 = fmaxf(rm1, __shfl_xor_sync(0xffffffffu, rm1, 2));

        float mn0 = fmaxf(m0, rm0), mn1 = fmaxf(m1, rm1);
        float a0 = ex2f(m0 - mn0), a1 = ex2f(m1 - mn1);
        m0 = mn0; m1 = mn1;

        float rs0 = 0.f, rs1 = 0.f;
        #pragma unroll
        for (int nt = 0; nt < 8; nt++) {
            s[nt][0] = ex2f(s[nt][0] - mn0);
            s[nt][1] = ex2f(s[nt][1] - mn0);
            s[nt][2] = ex2f(s[nt][2] - mn1);
            s[nt][3] = ex2f(s[nt][3] - mn1);
            rs0 += s[nt][0] + s[nt][1];
            rs1 += s[nt][2] + s[nt][3];
        }
        l0 = l0 * a0 + rs0;
        l1 = l1 * a1 + rs1;

        #pragma unroll
        for (int nt = 0; nt < 8; nt++) {
            o[nt][0] *= a0; o[nt][1] *= a0;
            o[nt][2] *= a1; o[nt][3] *= a1;
        }

        // --- O += P V ---
        #pragma unroll
        for (int k4 = 0; k4 < 4; k4++) {
            uint32_t pa[4];
            pa[0] = h2pack(s[2 * k4][0],     s[2 * k4][1]);
            pa[1] = h2pack(s[2 * k4][2],     s[2 * k4][3]);
            pa[2] = h2pack(s[2 * k4 + 1][0], s[2 * k4 + 1][1]);
            pa[3] = h2pack(s[2 * k4 + 1][2], s[2 * k4 + 1][3]);
            #pragma unroll
            for (int np = 0; np < 4; np++) {
                uint32_t vf[4];
                ldm_x4t(vf, &Vh[cur][(16 * k4 + vrow) * HSK + 16 * np + vcol8]);
                mma_f16(o[2 * np],     pa, vf[0], vf[1]);
                mma_f16(o[2 * np + 1], pa, vf[2], vf[3]);
            }
        }
    }

    // --- epilogue: reduce lane-partial l across the 4 qi lanes (exact) ---
    l0 += __shfl_xor_sync(0xffffffffu, l0, 1);
    l0 += __shfl_xor_sync(0xffffffffu, l0, 2);
    l1 += __shfl_xor_sync(0xffffffffu, l1, 1);
    l1 += __shfl_xor_sync(0xffffffffu, l1, 2);

    if (nch == 1) {
        float* Og = Out + ((size_t)b * TLEN + (size_t)qb * 64) * HD;
        float i0 = 1.f / l0, i1 = 1.f / l1;
        #pragma unroll
        for (int nt = 0; nt < 8; nt++) {
            int c0 = 8 * nt + 2 * qi;
            *(float2*)&Og[(size_t)qr * HD + c0] =
                make_float2(o[nt][0] * i0, o[nt][1] * i0);
            *(float2*)&Og[(size_t)(qr + 8) * HD + c0] =
                make_float2(o[nt][2] * i1, o[nt][3] * i1);
        }
        return;
    }

    // --- write unnormalized partial + (m, l) ---
    const int qt = b * 64 + qb;
    const size_t pi = ((size_t)qt * MAXNCH + chunk);
    float* Po = g_Po + pi * 64 * 64;
    #pragma unroll
    for (int nt = 0; nt < 8; nt++) {
        int c0 = 8 * nt + 2 * qi;
        *(float2*)&Po[(size_t)qr * 64 + c0] = make_float2(o[nt][0], o[nt][1]);
        *(float2*)&Po[(size_t)(qr + 8) * 64 + c0] = make_float2(o[nt][2], o[nt][3]);
    }
    if (qi == 0) {
        g_Pm[pi * 64 + qr]     = m0;
        g_Pl[pi * 64 + qr]     = l0;
        g_Pm[pi * 64 + qr + 8] = m1;
        g_Pl[pi * 64 + qr + 8] = l1;
    }

    // --- last-CTA-done detection ---
    __threadfence();
    if (tid == 0) {
        int old = atomicAdd(&g_cnt[qt], 1);
        s_last = (old == nch - 1) ? 1 : 0;
    }
    __syncthreads();
    if (!s_last) return;

    // --- fused combine: this CTA reduces all nch chunks for this q-tile ---
    {
        const int row = tid >> 1;            // 0..63
        const int c0  = (tid & 1) * 32;      // 0 or 32
        float mv[MAXNCH], lv[MAXNCH];
        float mmax = -1e30f;
        for (int c = 0; c < nch; c++) {
            mv[c] = g_Pm[((size_t)qt * MAXNCH + c) * 64 + row];
            lv[c] = g_Pl[((size_t)qt * MAXNCH + c) * 64 + row];
            mmax = fmaxf(mmax, mv[c]);
        }
        float denom = 0.f;
        float w[MAXNCH];
        for (int c = 0; c < nch; c++) {
            w[c] = ex2f(mv[c] - mmax);
            denom += w[c] * lv[c];
        }
        const float inv = 1.f / denom;

        float4 acc[8];
        #pragma unroll
        for (int j = 0; j < 8; j++) acc[j] = make_float4(0.f, 0.f, 0.f, 0.f);

        for (int c = 0; c < nch; c++) {
            const float4* src = (const float4*)(g_Po +
                (((size_t)qt * MAXNCH + c) * 64 + row) * 64 + c0);
            float wc = w[c];
            #pragma unroll
            for (int j = 0; j < 8; j++) {
                float4 v = src[j];
                acc[j].x += wc * v.x; acc[j].y += wc * v.y;
                acc[j].z += wc * v.z; acc[j].w += wc * v.w;
            }
        }

        float4* dst = (float4*)(Out +
            ((size_t)b * TLEN + (size_t)qb * 64 + row) * HD + c0);
        #pragma unroll
        for (int j = 0; j < 8; j++) {
            dst[j] = make_float4(acc[j].x * inv, acc[j].y * inv,
                                 acc[j].z * inv, acc[j].w * inv);
        }
    }
}

// ---------------------------------------------------------------------------
extern "C" void kernel_launch(void* const* d_in, const int* in_sizes, int n_in,
                              void* d_out, int out_size)
{
    const float* x  = (const float*)d_in[0];
    const float* Wq = (const float*)d_in[1];
    const float* Wk = (const float*)d_in[2];
    const float* Wv = (const float*)d_in[3];
    float* out = (float*)d_out;

    const int smem_qkv  = (128 * XSK + 128 * WSK) * (int)sizeof(__half); // 86016
    const int smem_attn = 4 * 64 * HSK * (int)sizeof(__half);            // 36864

    cudaFuncSetAttribute(qkv_kernel,
        cudaFuncAttributeMaxDynamicSharedMemorySize, smem_qkv);
    cudaFuncSetAttribute(attn_kernel,
        cudaFuncAttributeMaxDynamicSharedMemorySize, smem_attn);

    cvt_kernel<<<1184, 256>>>(x, Wq, Wk, Wv);
    qkv_kernel<<<BT / 128, 256, smem_qkv>>>();
    attn_kernel<<<dim3(160, NB), 128, smem_attn>>>(out);
}

// round 16
// speedup vs baseline: 1.0773x; 1.0773x over previous
#include <cuda_runtime.h>
#include <cuda_fp16.h>
#include <math.h>
#include <float.h>
#include <stdint.h>

#define NB    8
#define TLEN  4096
#define BT    (NB * TLEN)   // 32768
#define DM    128
#define HD    64
#define HSK   72            // attn smem stride (halves); conflict-free ldmatrix
#define XSK   136           // qkv X fp16 smem stride (halves)
#define XFS   132           // qkv X fp32 smem stride (floats)
#define WSK   200           // qkv W smem stride (halves)
#define CH    16            // kv tiles per chunk CTA
#define MAXNCH 4            // max chunks per q-tile (64/CH)

// Scratch. Q pre-scaled by 1/sqrt(128)*log2(e). Everything fp16.
__device__ __half g_Wh[DM * 192];       // fused W fp16 [k][Q|K|V], Wq pre-scaled
__device__ __half g_Qh[BT * HD];
__device__ __half g_Kh[BT * HD];
__device__ __half g_Vh[BT * HD];

// Split-KV partials: O fp16 (unnormalized), m/l fp32
__device__ __half g_Ph[NB * 64 * MAXNCH * 64 * 64];   // 16.8 MB
__device__ float  g_Pm[NB * 64 * MAXNCH * 64];
__device__ float  g_Pl[NB * 64 * MAXNCH * 64];

// ---------------------------------------------------------------------------
// helpers
// ---------------------------------------------------------------------------
__device__ __forceinline__ float ex2f(float x) {
    float r;
    asm("ex2.approx.ftz.f32 %0, %1;" : "=f"(r) : "f"(x));
    return r;
}
__device__ __forceinline__ uint32_t h2pack(float a, float b) {
    __half2 h = __floats2half2_rn(a, b);
    return *(uint32_t*)&h;
}
__device__ __forceinline__ void mma_f16(float* d, const uint32_t* a,
                                        uint32_t b0, uint32_t b1) {
    asm volatile(
        "mma.sync.aligned.m16n8k16.row.col.f32.f16.f16.f32 "
        "{%0,%1,%2,%3}, {%4,%5,%6,%7}, {%8,%9}, {%0,%1,%2,%3};\n"
        : "+f"(d[0]), "+f"(d[1]), "+f"(d[2]), "+f"(d[3])
        : "r"(a[0]), "r"(a[1]), "r"(a[2]), "r"(a[3]), "r"(b0), "r"(b1));
}
__device__ __forceinline__ void ldm_x4(uint32_t* r, const void* p) {
    uint32_t a = (uint32_t)__cvta_generic_to_shared(p);
    asm volatile("ldmatrix.sync.aligned.m8n8.x4.shared.b16 {%0,%1,%2,%3}, [%4];"
        : "=r"(r[0]), "=r"(r[1]), "=r"(r[2]), "=r"(r[3]) : "r"(a));
}
__device__ __forceinline__ void ldm_x4t(uint32_t* r, const void* p) {
    uint32_t a = (uint32_t)__cvta_generic_to_shared(p);
    asm volatile("ldmatrix.sync.aligned.m8n8.x4.trans.shared.b16 {%0,%1,%2,%3}, [%4];"
        : "=r"(r[0]), "=r"(r[1]), "=r"(r[2]), "=r"(r[3]) : "r"(a));
}
__device__ __forceinline__ void cpa16(void* dst, const void* src) {
    uint32_t d = (uint32_t)__cvta_generic_to_shared(dst);
    asm volatile("cp.async.cg.shared.global [%0], [%1], 16;" :: "r"(d), "l"(src));
}
#define CP_COMMIT() asm volatile("cp.async.commit_group;")
#define CP_WAIT0()  asm volatile("cp.async.wait_group 0;" ::: "memory")

// softmax scale folded into Wq: 1/sqrt(128) * log2(e)
#define QSCL (0.08838834764831845f * 1.4426950408889634f)

// ---------------------------------------------------------------------------
// Tiny W conversion: fused fp16 W, Wq pre-scaled. 24 CTAs x 256 thr.
// ---------------------------------------------------------------------------
__global__ __launch_bounds__(256) void cvtw_kernel(
    const float* __restrict__ Wq,
    const float* __restrict__ Wk,
    const float* __restrict__ Wv)
{
    const int i = blockIdx.x * 256 + threadIdx.x;   // one float4-quad each
    if (i >= DM * 192 / 4) return;
    int k = (4 * i) / 192;
    int c = (4 * i) % 192;
    const float* src;
    float sc;
    if (c < 64)       { src = Wq + k * 64 + c;         sc = QSCL; }
    else if (c < 128) { src = Wk + k * 64 + (c - 64);  sc = 1.0f; }
    else              { src = Wv + k * 64 + (c - 128); sc = 1.0f; }
    float4 v = *(const float4*)src;
    uint2 h;
    h.x = h2pack(v.x * sc, v.y * sc);
    h.y = h2pack(v.z * sc, v.w * sc);
    *(uint2*)&g_Wh[k * 192 + c] = h;
}

// ---------------------------------------------------------------------------
// QKV projection: fp32 x staged directly via cp.async, converted in-CTA,
// fp16 smem GEMM. CTA = 64 x-rows, 256 thr = 8 warps (2 CTAs/SM).
// warp (rg=w>>1, cg=w&1): rows 16*rg..+15, cols 96*cg..+95.
// ---------------------------------------------------------------------------
__global__ __launch_bounds__(256, 2) void qkv_kernel(const float* __restrict__ x)
{
    extern __shared__ float smf[];
    float*  Xf = smf;                           // [64][XFS] fp32
    __half* Xh = (__half*)(smf + 64 * XFS);     // [64][XSK] fp16
    __half* Ws = Xh + 64 * XSK;                 // [128][WSK] fp16

    const int tid  = threadIdx.x;
    const int row0 = blockIdx.x * 64;

    // stage x fp32 (64 rows x 32 float4) + W fp16 (128 k x 24 chunks)
    #pragma unroll
    for (int idx = tid; idx < 64 * 32; idx += 256) {
        int r = idx >> 5, c4 = (idx & 31) * 4;
        cpa16(&Xf[r * XFS + c4], x + (size_t)(row0 + r) * DM + c4);
    }
    #pragma unroll
    for (int idx = tid; idx < 128 * 24; idx += 256) {
        int k = idx / 24, c8 = (idx % 24) * 8;
        cpa16(&Ws[k * WSK + c8], g_Wh + k * 192 + c8);
    }
    CP_COMMIT();
    CP_WAIT0();
    __syncthreads();

    // convert x fp32 -> fp16 in smem (warp reads one row sequentially)
    #pragma unroll
    for (int idx = tid; idx < 64 * 32; idx += 256) {
        int r = idx >> 5, c4 = (idx & 31) * 4;
        float4 v = *(const float4*)&Xf[r * XFS + c4];
        uint2 h;
        h.x = h2pack(v.x, v.y);
        h.y = h2pack(v.z, v.w);
        *(uint2*)&Xh[r * XSK + c4] = h;
    }
    __syncthreads();

    const int warp = tid >> 5, lane = tid & 31;
    const int g = lane >> 2, qi = lane & 3;
    const int rowbase = 16 * (warp >> 1);
    const int colbase = 96 * (warp & 1);
    const int arow  = ((lane >> 3) & 1) * 8 + (lane & 7);
    const int acol8 = (lane >> 4) * 8;
    const int wrow  = ((lane >> 3) & 1) * 8 + (lane & 7);
    const int wcol8 = (lane >> 4) * 8;

    float s[12][4];
    #pragma unroll
    for (int nt = 0; nt < 12; nt++)
        #pragma unroll
        for (int e = 0; e < 4; e++) s[nt][e] = 0.f;

    #pragma unroll
    for (int ks = 0; ks < 8; ks++) {
        uint32_t qa[4];
        ldm_x4(qa, &Xh[(rowbase + arow) * XSK + 16 * ks + acol8]);
        #pragma unroll
        for (int np = 0; np < 6; np++) {
            uint32_t wf[4];
            ldm_x4t(wf, &Ws[(16 * ks + wrow) * WSK + colbase + 16 * np + wcol8]);
            mma_f16(s[2 * np],     qa, wf[0], wf[1]);
            mma_f16(s[2 * np + 1], qa, wf[2], wf[3]);
        }
    }

    // scatter outputs fp16 (half2 coalesced)
    #pragma unroll
    for (int nt = 0; nt < 12; nt++) {
        int c0 = colbase + 8 * nt + 2 * qi;
        int rA = row0 + rowbase + g;
        #pragma unroll
        for (int half = 0; half < 2; half++) {
            int r = rA + 8 * half;
            __half2 hv = __floats2half2_rn(s[nt][2 * half + 0],
                                           s[nt][2 * half + 1]);
            if (c0 < 64) {
                *(__half2*)&g_Qh[(size_t)r * HD + c0] = hv;
            } else if (c0 < 128) {
                *(__half2*)&g_Kh[(size_t)r * HD + (c0 - 64)] = hv;
            } else {
                *(__half2*)&g_Vh[(size_t)r * HD + (c0 - 128)] = hv;
            }
        }
    }
}

// ---------------------------------------------------------------------------
// Causal flash attention, split-KV CH=16 (R14-proven inner loop).
// Partials stored fp16 (unnormalized O) + fp32 m/l.
// ---------------------------------------------------------------------------
__global__ __launch_bounds__(128, 4) void attn_kernel(float* __restrict__ Out)
{
    extern __shared__ float sm[];
    __half* base = (__half*)sm;
    __half* Kb[2] = { base,                base + 64 * HSK };
    __half* Vh[2] = { base + 2 * 64 * HSK, base + 3 * 64 * HSK };

    // map work unit -> (qb, chunk); biggest chunks scheduled first
    const int wu = 159 - (int)blockIdx.x;
    int gI = 0;
    while (wu >= 8 * (gI + 1) * (gI + 2)) gI++;       // offsets[g] = 8g(g+1)
    const int rem   = wu - 8 * gI * (gI + 1);
    const int qb    = 16 * gI + rem / (gI + 1);
    const int chunk = rem % (gI + 1);
    const int nch   = qb / CH + 1;
    const int t0 = chunk * CH;
    const int t1 = min(t0 + CH, qb + 1);

    const int b    = blockIdx.y;
    const int tid  = threadIdx.x;
    const int warp = tid >> 5, lane = tid & 31;
    const int g    = lane >> 2, qi = lane & 3;

    const int arow  = ((lane >> 3) & 1) * 8 + (lane & 7);
    const int acol8 = (lane >> 4) * 8;
    const int krow  = (lane & 7) + ((lane >> 4) << 3);
    const int kcol8 = ((lane >> 3) & 1) * 8;
    const int vrow  = ((lane >> 3) & 1) * 8 + (lane & 7);
    const int vcol8 = (lane >> 4) * 8;

    const __half* Kg0 = g_Kh + (size_t)b * TLEN * HD;
    const __half* Vg0 = g_Vh + (size_t)b * TLEN * HD;

    // preload K(t0)+V(t0) as one group
    #pragma unroll
    for (int idx = tid; idx < 64 * 8; idx += 128) {
        int r = idx >> 3, c8 = (idx & 7) * 8;
        cpa16(&Kb[0][r * HSK + c8], Kg0 + (size_t)(t0 * 64 + r) * HD + c8);
        cpa16(&Vh[0][r * HSK + c8], Vg0 + (size_t)(t0 * 64 + r) * HD + c8);
    }
    CP_COMMIT();

    // stage Q (fp16, pre-scaled) into Kb[1], pull A-fragments
    const __half* Qg = g_Qh + ((size_t)b * TLEN + (size_t)qb * 64) * HD;
    #pragma unroll
    for (int idx = tid; idx < 64 * 8; idx += 128) {
        int r = idx >> 3, c8 = (idx & 7) * 8;
        *(uint4*)&Kb[1][r * HSK + c8] = *(const uint4*)(Qg + (size_t)r * HD + c8);
    }
    __syncthreads();

    uint32_t qa[4][4];
    #pragma unroll
    for (int ks = 0; ks < 4; ks++)
        ldm_x4(qa[ks], &Kb[1][(16 * warp + arow) * HSK + 16 * ks + acol8]);

    float o[8][4];
    #pragma unroll
    for (int nt = 0; nt < 8; nt++)
        #pragma unroll
        for (int e = 0; e < 4; e++) o[nt][e] = 0.f;
    float m0 = -1e30f, m1 = -1e30f, l0 = 0.f, l1 = 0.f;  // l: lane-partial

    const int qr = 16 * warp + g;

    for (int kb = t0; kb < t1; kb++) {
        const int cur = (kb - t0) & 1;

        CP_WAIT0();
        __syncthreads();

        if (kb + 1 < t1) {
            const __half* Kg = Kg0 + (size_t)(kb + 1) * 64 * HD;
            const __half* Vg = Vg0 + (size_t)(kb + 1) * 64 * HD;
            #pragma unroll
            for (int idx = tid; idx < 64 * 8; idx += 128) {
                int r = idx >> 3, c8 = (idx & 7) * 8;
                cpa16(&Kb[1 - cur][r * HSK + c8], Kg + (size_t)r * HD + c8);
                cpa16(&Vh[1 - cur][r * HSK + c8], Vg + (size_t)r * HD + c8);
            }
        }
        CP_COMMIT();

        // --- S = Q K^T ---
        float s[8][4];
        #pragma unroll
        for (int nt = 0; nt < 8; nt++)
            #pragma unroll
            for (int e = 0; e < 4; e++) s[nt][e] = 0.f;

        #pragma unroll
        for (int ks = 0; ks < 4; ks++) {
            #pragma unroll
            for (int ntp = 0; ntp < 4; ntp++) {
                uint32_t kf[4];
                ldm_x4(kf, &Kb[cur][(16 * ntp + krow) * HSK + 16 * ks + kcol8]);
                mma_f16(s[2 * ntp],     qa[ks], kf[0], kf[1]);
                mma_f16(s[2 * ntp + 1], qa[ks], kf[2], kf[3]);
            }
        }

        // --- causal mask: diagonal tile only ---
        if (kb == qb) {
            #pragma unroll
            for (int nt = 0; nt < 8; nt++) {
                int c0 = 8 * nt + 2 * qi;
                if (c0     > qr    ) s[nt][0] = -1e30f;
                if (c0 + 1 > qr    ) s[nt][1] = -1e30f;
                if (c0     > qr + 8) s[nt][2] = -1e30f;
                if (c0 + 1 > qr + 8) s[nt][3] = -1e30f;
            }
        }

        // --- online softmax (exp2 domain); l lane-partial ---
        float rm0 = -1e30f, rm1 = -1e30f;
        #pragma unroll
        for (int nt = 0; nt < 8; nt++) {
            rm0 = fmaxf(rm0, fmaxf(s[nt][0], s[nt][1]));
            rm1 = fmaxf(rm1, fmaxf(s[nt][2], s[nt][3]));
        }
        rm0 = fmaxf(rm0, __shfl_xor_sync(0xffffffffu, rm0, 1));
        rm0 = fmaxf(rm0, __shfl_xor_sync(0xffffffffu, rm0, 2));
        rm1 = fmaxf(rm1, __shfl_xor_sync(0xffffffffu, rm1, 1));
        rm1 = fmaxf(rm1, __shfl_xor_sync(0xffffffffu, rm1, 2));

        float mn0 = fmaxf(m0, rm0), mn1 = fmaxf(m1, rm1);
        float a0 = ex2f(m0 - mn0), a1 = ex2f(m1 - mn1);
        m0 = mn0; m1 = mn1;

        float rs0 = 0.f, rs1 = 0.f;
        #pragma unroll
        for (int nt = 0; nt < 8; nt++) {
            s[nt][0] = ex2f(s[nt][0] - mn0);
            s[nt][1] = ex2f(s[nt][1] - mn0);
            s[nt][2] = ex2f(s[nt][2] - mn1);
            s[nt][3] = ex2f(s[nt][3] - mn1);
            rs0 += s[nt][0] + s[nt][1];
            rs1 += s[nt][2] + s[nt][3];
        }
        l0 = l0 * a0 + rs0;
        l1 = l1 * a1 + rs1;

        #pragma unroll
        for (int nt = 0; nt < 8; nt++) {
            o[nt][0] *= a0; o[nt][1] *= a0;
            o[nt][2] *= a1; o[nt][3] *= a1;
        }

        // --- O += P V ---
        #pragma unroll
        for (int k4 = 0; k4 < 4; k4++) {
            uint32_t pa[4];
            pa[0] = h2pack(s[2 * k4][0],     s[2 * k4][1]);
            pa[1] = h2pack(s[2 * k4][2],     s[2 * k4][3]);
            pa[2] = h2pack(s[2 * k4 + 1][0], s[2 * k4 + 1][1]);
            pa[3] = h2pack(s[2 * k4 + 1][2], s[2 * k4 + 1][3]);
            #pragma unroll
            for (int np = 0; np < 4; np++) {
                uint32_t vf[4];
                ldm_x4t(vf, &Vh[cur][(16 * k4 + vrow) * HSK + 16 * np + vcol8]);
                mma_f16(o[2 * np],     pa, vf[0], vf[1]);
                mma_f16(o[2 * np + 1], pa, vf[2], vf[3]);
            }
        }
    }

    // --- epilogue: reduce lane-partial l across the 4 qi lanes (exact) ---
    l0 += __shfl_xor_sync(0xffffffffu, l0, 1);
    l0 += __shfl_xor_sync(0xffffffffu, l0, 2);
    l1 += __shfl_xor_sync(0xffffffffu, l1, 1);
    l1 += __shfl_xor_sync(0xffffffffu, l1, 2);

    if (nch == 1) {
        float* Og = Out + ((size_t)b * TLEN + (size_t)qb * 64) * HD;
        float i0 = 1.f / l0, i1 = 1.f / l1;
        #pragma unroll
        for (int nt = 0; nt < 8; nt++) {
            int c0 = 8 * nt + 2 * qi;
            *(float2*)&Og[(size_t)qr * HD + c0] =
                make_float2(o[nt][0] * i0, o[nt][1] * i0);
            *(float2*)&Og[(size_t)(qr + 8) * HD + c0] =
                make_float2(o[nt][2] * i1, o[nt][3] * i1);
        }
    } else {
        const size_t pi = ((size_t)(b * 64 + qb) * MAXNCH + chunk);
        __half* Po = g_Ph + pi * 64 * 64;
        #pragma unroll
        for (int nt = 0; nt < 8; nt++) {
            int c0 = 8 * nt + 2 * qi;
            *(__half2*)&Po[(size_t)qr * 64 + c0] =
                __floats2half2_rn(o[nt][0], o[nt][1]);
            *(__half2*)&Po[(size_t)(qr + 8) * 64 + c0] =
                __floats2half2_rn(o[nt][2], o[nt][3]);
        }
        if (qi == 0) {
            g_Pm[pi * 64 + qr]     = m0;
            g_Pl[pi * 64 + qr]     = l0;
            g_Pm[pi * 64 + qr + 8] = m1;
            g_Pl[pi * 64 + qr + 8] = l1;
        }
    }
}

// ---------------------------------------------------------------------------
// Combine fp16 partials for qb >= CH. Grid (64-CH, NB), 256 threads.
// ---------------------------------------------------------------------------
__global__ __launch_bounds__(256) void combine_kernel(float* __restrict__ Out)
{
    const int qb  = CH + (int)blockIdx.x;     // 16..63
    const int b   = blockIdx.y;
    const int nch = qb / CH + 1;              // 2..4
    const int tid = threadIdx.x;
    const int row = tid >> 2;
    const int c0  = (tid & 3) * 16;
    const size_t qt = (size_t)(b * 64 + qb);

    float mv[MAXNCH], lv[MAXNCH];
    float mmax = -1e30f;
    for (int c = 0; c < nch; c++) {
        mv[c] = g_Pm[(qt * MAXNCH + c) * 64 + row];
        lv[c] = g_Pl[(qt * MAXNCH + c) * 64 + row];
        mmax = fmaxf(mmax, mv[c]);
    }
    float denom = 0.f;
    float w[MAXNCH];
    for (int c = 0; c < nch; c++) {
        w[c] = ex2f(mv[c] - mmax);
        denom += w[c] * lv[c];
    }
    const float inv = 1.f / denom;

    float acc[16];
    #pragma unroll
    for (int j = 0; j < 16; j++) acc[j] = 0.f;

    for (int c = 0; c < nch; c++) {
        const uint4* src = (const uint4*)(g_Ph +
            ((qt * MAXNCH + c) * 64 + row) * 64 + c0);
        float wc = w[c];
        #pragma unroll
        for (int q = 0; q < 2; q++) {        // 2 x uint4 = 16 halves
            uint4 u = src[q];
            const uint32_t uw[4] = {u.x, u.y, u.z, u.w};
            #pragma unroll
            for (int p = 0; p < 4; p++) {
                __half2 hv = *(const __half2*)&uw[p];
                float2 f = __half22float2(hv);
                acc[q * 8 + 2 * p]     += wc * f.x;
                acc[q * 8 + 2 * p + 1] += wc * f.y;
            }
        }
    }

    float4* dst = (float4*)(Out + ((size_t)b * TLEN + (size_t)qb * 64 + row) * HD + c0);
    #pragma unroll
    for (int j = 0; j < 4; j++) {
        dst[j] = make_float4(acc[4 * j]     * inv, acc[4 * j + 1] * inv,
                             acc[4 * j + 2] * inv, acc[4 * j + 3] * inv);
    }
}

// ---------------------------------------------------------------------------
extern "C" void kernel_launch(void* const* d_in, const int* in_sizes, int n_in,
                              void* d_out, int out_size)
{
    const float* x  = (const float*)d_in[0];
    const float* Wq = (const float*)d_in[1];
    const float* Wk = (const float*)d_in[2];
    const float* Wv = (const float*)d_in[3];
    float* out = (float*)d_out;

    const int smem_qkv  = 64 * XFS * (int)sizeof(float)
                        + (64 * XSK + 128 * WSK) * (int)sizeof(__half); // 102400
    const int smem_attn = 4 * 64 * HSK * (int)sizeof(__half);           // 36864

    cudaFuncSetAttribute(qkv_kernel,
        cudaFuncAttributeMaxDynamicSharedMemorySize, smem_qkv);
    cudaFuncSetAttribute(attn_kernel,
        cudaFuncAttributeMaxDynamicSharedMemorySize, smem_attn);

    cvtw_kernel<<<24, 256>>>(Wq, Wk, Wv);
    qkv_kernel<<<BT / 64, 256, smem_qkv>>>(x);
    attn_kernel<<<dim3(160, NB), 128, smem_attn>>>(out);
    combine_kernel<<<dim3(64 - CH, NB), 256>>>(out);
}

// round 17
// speedup vs baseline: 1.1022x; 1.0230x over previous
#include <cuda_runtime.h>
#include <cuda_fp16.h>
#include <math.h>
#include <float.h>
#include <stdint.h>

#define NB    8
#define TLEN  4096
#define BT    (NB * TLEN)   // 32768
#define DM    128
#define HD    64
#define HSK   72            // attn smem stride (halves); conflict-free ldmatrix
#define XSK   136           // qkv X fp16 smem stride (halves)
#define XFS   132           // qkv X fp32 smem stride (floats)
#define WSK   200           // qkv W smem stride (halves)
#define CH    16            // kv tiles per chunk CTA
#define MAXNCH 4            // max chunks per q-tile (64/CH)

// Scratch. Q pre-scaled by 1/sqrt(128)*log2(e). Everything fp16.
__device__ __half g_Wh[DM * 192];       // fused W fp16 [k][Q|K|V], Wq pre-scaled
__device__ __half g_Qh[BT * HD];
__device__ __half g_Kh[BT * HD];
__device__ __half g_Vh[BT * HD];

// Split-KV partials: O fp16 (unnormalized), m/l fp32
__device__ __half g_Ph[NB * 64 * MAXNCH * 64 * 64];   // 16.8 MB
__device__ float  g_Pm[NB * 64 * MAXNCH * 64];
__device__ float  g_Pl[NB * 64 * MAXNCH * 64];

// ---------------------------------------------------------------------------
// helpers
// ---------------------------------------------------------------------------
__device__ __forceinline__ float ex2f(float x) {
    float r;
    asm("ex2.approx.ftz.f32 %0, %1;" : "=f"(r) : "f"(x));
    return r;
}
__device__ __forceinline__ uint32_t h2pack(float a, float b) {
    __half2 h = __floats2half2_rn(a, b);
    return *(uint32_t*)&h;
}
__device__ __forceinline__ void mma_f16(float* d, const uint32_t* a,
                                        uint32_t b0, uint32_t b1) {
    asm volatile(
        "mma.sync.aligned.m16n8k16.row.col.f32.f16.f16.f32 "
        "{%0,%1,%2,%3}, {%4,%5,%6,%7}, {%8,%9}, {%0,%1,%2,%3};\n"
        : "+f"(d[0]), "+f"(d[1]), "+f"(d[2]), "+f"(d[3])
        : "r"(a[0]), "r"(a[1]), "r"(a[2]), "r"(a[3]), "r"(b0), "r"(b1));
}
__device__ __forceinline__ void ldm_x4(uint32_t* r, const void* p) {
    uint32_t a = (uint32_t)__cvta_generic_to_shared(p);
    asm volatile("ldmatrix.sync.aligned.m8n8.x4.shared.b16 {%0,%1,%2,%3}, [%4];"
        : "=r"(r[0]), "=r"(r[1]), "=r"(r[2]), "=r"(r[3]) : "r"(a));
}
__device__ __forceinline__ void ldm_x4t(uint32_t* r, const void* p) {
    uint32_t a = (uint32_t)__cvta_generic_to_shared(p);
    asm volatile("ldmatrix.sync.aligned.m8n8.x4.trans.shared.b16 {%0,%1,%2,%3}, [%4];"
        : "=r"(r[0]), "=r"(r[1]), "=r"(r[2]), "=r"(r[3]) : "r"(a));
}
__device__ __forceinline__ void cpa16(void* dst, const void* src) {
    uint32_t d = (uint32_t)__cvta_generic_to_shared(dst);
    asm volatile("cp.async.cg.shared.global [%0], [%1], 16;" :: "r"(d), "l"(src));
}
#define CP_COMMIT() asm volatile("cp.async.commit_group;")
#define CP_WAIT0()  asm volatile("cp.async.wait_group 0;" ::: "memory")

// softmax scale folded into Wq: 1/sqrt(128) * log2(e)
#define QSCL (0.08838834764831845f * 1.4426950408889634f)

// ---------------------------------------------------------------------------
// Tiny W conversion: fused fp16 W, Wq pre-scaled. 24 CTAs x 256 thr.
// ---------------------------------------------------------------------------
__global__ __launch_bounds__(256) void cvtw_kernel(
    const float* __restrict__ Wq,
    const float* __restrict__ Wk,
    const float* __restrict__ Wv)
{
    const int i = blockIdx.x * 256 + threadIdx.x;   // one float4-quad each
    if (i >= DM * 192 / 4) return;
    int k = (4 * i) / 192;
    int c = (4 * i) % 192;
    const float* src;
    float sc;
    if (c < 64)       { src = Wq + k * 64 + c;         sc = QSCL; }
    else if (c < 128) { src = Wk + k * 64 + (c - 64);  sc = 1.0f; }
    else              { src = Wv + k * 64 + (c - 128); sc = 1.0f; }
    float4 v = *(const float4*)src;
    uint2 h;
    h.x = h2pack(v.x * sc, v.y * sc);
    h.y = h2pack(v.z * sc, v.w * sc);
    *(uint2*)&g_Wh[k * 192 + c] = h;
}

// ---------------------------------------------------------------------------
// QKV projection: fp32 x staged directly via cp.async, converted in-CTA,
// fp16 smem GEMM. CTA = 64 x-rows, 256 thr = 8 warps (2 CTAs/SM).
// ---------------------------------------------------------------------------
__global__ __launch_bounds__(256, 2) void qkv_kernel(const float* __restrict__ x)
{
    extern __shared__ float smf[];
    float*  Xf = smf;                           // [64][XFS] fp32
    __half* Xh = (__half*)(smf + 64 * XFS);     // [64][XSK] fp16
    __half* Ws = Xh + 64 * XSK;                 // [128][WSK] fp16

    const int tid  = threadIdx.x;
    const int row0 = blockIdx.x * 64;

    #pragma unroll
    for (int idx = tid; idx < 64 * 32; idx += 256) {
        int r = idx >> 5, c4 = (idx & 31) * 4;
        cpa16(&Xf[r * XFS + c4], x + (size_t)(row0 + r) * DM + c4);
    }
    #pragma unroll
    for (int idx = tid; idx < 128 * 24; idx += 256) {
        int k = idx / 24, c8 = (idx % 24) * 8;
        cpa16(&Ws[k * WSK + c8], g_Wh + k * 192 + c8);
    }
    CP_COMMIT();
    CP_WAIT0();
    __syncthreads();

    #pragma unroll
    for (int idx = tid; idx < 64 * 32; idx += 256) {
        int r = idx >> 5, c4 = (idx & 31) * 4;
        float4 v = *(const float4*)&Xf[r * XFS + c4];
        uint2 h;
        h.x = h2pack(v.x, v.y);
        h.y = h2pack(v.z, v.w);
        *(uint2*)&Xh[r * XSK + c4] = h;
    }
    __syncthreads();

    const int warp = tid >> 5, lane = tid & 31;
    const int g = lane >> 2, qi = lane & 3;
    const int rowbase = 16 * (warp >> 1);
    const int colbase = 96 * (warp & 1);
    const int arow  = ((lane >> 3) & 1) * 8 + (lane & 7);
    const int acol8 = (lane >> 4) * 8;
    const int wrow  = ((lane >> 3) & 1) * 8 + (lane & 7);
    const int wcol8 = (lane >> 4) * 8;

    float s[12][4];
    #pragma unroll
    for (int nt = 0; nt < 12; nt++)
        #pragma unroll
        for (int e = 0; e < 4; e++) s[nt][e] = 0.f;

    #pragma unroll
    for (int ks = 0; ks < 8; ks++) {
        uint32_t qa[4];
        ldm_x4(qa, &Xh[(rowbase + arow) * XSK + 16 * ks + acol8]);
        #pragma unroll
        for (int np = 0; np < 6; np++) {
            uint32_t wf[4];
            ldm_x4t(wf, &Ws[(16 * ks + wrow) * WSK + colbase + 16 * np + wcol8]);
            mma_f16(s[2 * np],     qa, wf[0], wf[1]);
            mma_f16(s[2 * np + 1], qa, wf[2], wf[3]);
        }
    }

    #pragma unroll
    for (int nt = 0; nt < 12; nt++) {
        int c0 = colbase + 8 * nt + 2 * qi;
        int rA = row0 + rowbase + g;
        #pragma unroll
        for (int half = 0; half < 2; half++) {
            int r = rA + 8 * half;
            __half2 hv = __floats2half2_rn(s[nt][2 * half + 0],
                                           s[nt][2 * half + 1]);
            if (c0 < 64) {
                *(__half2*)&g_Qh[(size_t)r * HD + c0] = hv;
            } else if (c0 < 128) {
                *(__half2*)&g_Kh[(size_t)r * HD + (c0 - 64)] = hv;
            } else {
                *(__half2*)&g_Vh[(size_t)r * HD + (c0 - 128)] = hv;
            }
        }
    }
}

// ---------------------------------------------------------------------------
// Causal flash attention, split-KV CH=16 (proven inner loop).
// Partials stored fp16 (unnormalized O) + fp32 m/l.
// ---------------------------------------------------------------------------
__global__ __launch_bounds__(128, 4) void attn_kernel(float* __restrict__ Out)
{
    extern __shared__ float sm[];
    __half* base = (__half*)sm;
    __half* Kb[2] = { base,                base + 64 * HSK };
    __half* Vh[2] = { base + 2 * 64 * HSK, base + 3 * 64 * HSK };

    // map work unit -> (qb, chunk); biggest chunks scheduled first
    const int wu = 159 - (int)blockIdx.x;
    int gI = 0;
    while (wu >= 8 * (gI + 1) * (gI + 2)) gI++;       // offsets[g] = 8g(g+1)
    const int rem   = wu - 8 * gI * (gI + 1);
    const int qb    = 16 * gI + rem / (gI + 1);
    const int chunk = rem % (gI + 1);
    const int nch   = qb / CH + 1;
    const int t0 = chunk * CH;
    const int t1 = min(t0 + CH, qb + 1);

    const int b    = blockIdx.y;
    const int tid  = threadIdx.x;
    const int warp = tid >> 5, lane = tid & 31;
    const int g    = lane >> 2, qi = lane & 3;

    const int arow  = ((lane >> 3) & 1) * 8 + (lane & 7);
    const int acol8 = (lane >> 4) * 8;
    const int krow  = (lane & 7) + ((lane >> 4) << 3);
    const int kcol8 = ((lane >> 3) & 1) * 8;
    const int vrow  = ((lane >> 3) & 1) * 8 + (lane & 7);
    const int vcol8 = (lane >> 4) * 8;

    const __half* Kg0 = g_Kh + (size_t)b * TLEN * HD;
    const __half* Vg0 = g_Vh + (size_t)b * TLEN * HD;

    #pragma unroll
    for (int idx = tid; idx < 64 * 8; idx += 128) {
        int r = idx >> 3, c8 = (idx & 7) * 8;
        cpa16(&Kb[0][r * HSK + c8], Kg0 + (size_t)(t0 * 64 + r) * HD + c8);
        cpa16(&Vh[0][r * HSK + c8], Vg0 + (size_t)(t0 * 64 + r) * HD + c8);
    }
    CP_COMMIT();

    const __half* Qg = g_Qh + ((size_t)b * TLEN + (size_t)qb * 64) * HD;
    #pragma unroll
    for (int idx = tid; idx < 64 * 8; idx += 128) {
        int r = idx >> 3, c8 = (idx & 7) * 8;
        *(uint4*)&Kb[1][r * HSK + c8] = *(const uint4*)(Qg + (size_t)r * HD + c8);
    }
    __syncthreads();

    uint32_t qa[4][4];
    #pragma unroll
    for (int ks = 0; ks < 4; ks++)
        ldm_x4(qa[ks], &Kb[1][(16 * warp + arow) * HSK + 16 * ks + acol8]);

    float o[8][4];
    #pragma unroll
    for (int nt = 0; nt < 8; nt++)
        #pragma unroll
        for (int e = 0; e < 4; e++) o[nt][e] = 0.f;
    float m0 = -1e30f, m1 = -1e30f, l0 = 0.f, l1 = 0.f;  // l: lane-partial

    const int qr = 16 * warp + g;

    for (int kb = t0; kb < t1; kb++) {
        const int cur = (kb - t0) & 1;

        CP_WAIT0();
        __syncthreads();

        if (kb + 1 < t1) {
            const __half* Kg = Kg0 + (size_t)(kb + 1) * 64 * HD;
            const __half* Vg = Vg0 + (size_t)(kb + 1) * 64 * HD;
            #pragma unroll
            for (int idx = tid; idx < 64 * 8; idx += 128) {
                int r = idx >> 3, c8 = (idx & 7) * 8;
                cpa16(&Kb[1 - cur][r * HSK + c8], Kg + (size_t)r * HD + c8);
                cpa16(&Vh[1 - cur][r * HSK + c8], Vg + (size_t)r * HD + c8);
            }
        }
        CP_COMMIT();

        // --- S = Q K^T ---
        float s[8][4];
        #pragma unroll
        for (int nt = 0; nt < 8; nt++)
            #pragma unroll
            for (int e = 0; e < 4; e++) s[nt][e] = 0.f;

        #pragma unroll
        for (int ks = 0; ks < 4; ks++) {
            #pragma unroll
            for (int ntp = 0; ntp < 4; ntp++) {
                uint32_t kf[4];
                ldm_x4(kf, &Kb[cur][(16 * ntp + krow) * HSK + 16 * ks + kcol8]);
                mma_f16(s[2 * ntp],     qa[ks], kf[0], kf[1]);
                mma_f16(s[2 * ntp + 1], qa[ks], kf[2], kf[3]);
            }
        }

        // --- causal mask: diagonal tile only ---
        if (kb == qb) {
            #pragma unroll
            for (int nt = 0; nt < 8; nt++) {
                int c0 = 8 * nt + 2 * qi;
                if (c0     > qr    ) s[nt][0] = -1e30f;
                if (c0 + 1 > qr    ) s[nt][1] = -1e30f;
                if (c0     > qr + 8) s[nt][2] = -1e30f;
                if (c0 + 1 > qr + 8) s[nt][3] = -1e30f;
            }
        }

        // --- online softmax (exp2 domain); l lane-partial ---
        float rm0 = -1e30f, rm1 = -1e30f;
        #pragma unroll
        for (int nt = 0; nt < 8; nt++) {
            rm0 = fmaxf(rm0, fmaxf(s[nt][0], s[nt][1]));
            rm1 = fmaxf(rm1, fmaxf(s[nt][2], s[nt][3]));
        }
        rm0 = fmaxf(rm0, __shfl_xor_sync(0xffffffffu, rm0, 1));
        rm0 = fmaxf(rm0, __shfl_xor_sync(0xffffffffu, rm0, 2));
        rm1 = fmaxf(rm1, __shfl_xor_sync(0xffffffffu, rm1, 1));
        rm1 = fmaxf(rm1, __shfl_xor_sync(0xffffffffu, rm1, 2));

        float mn0 = fmaxf(m0, rm0), mn1 = fmaxf(m1, rm1);
        float a0 = ex2f(m0 - mn0), a1 = ex2f(m1 - mn1);
        m0 = mn0; m1 = mn1;

        float rs0 = 0.f, rs1 = 0.f;
        #pragma unroll
        for (int nt = 0; nt < 8; nt++) {
            s[nt][0] = ex2f(s[nt][0] - mn0);
            s[nt][1] = ex2f(s[nt][1] - mn0);
            s[nt][2] = ex2f(s[nt][2] - mn1);
            s[nt][3] = ex2f(s[nt][3] - mn1);
            rs0 += s[nt][0] + s[nt][1];
            rs1 += s[nt][2] + s[nt][3];
        }
        l0 = l0 * a0 + rs0;
        l1 = l1 * a1 + rs1;

        #pragma unroll
        for (int nt = 0; nt < 8; nt++) {
            o[nt][0] *= a0; o[nt][1] *= a0;
            o[nt][2] *= a1; o[nt][3] *= a1;
        }

        // --- O += P V ---
        #pragma unroll
        for (int k4 = 0; k4 < 4; k4++) {
            uint32_t pa[4];
            pa[0] = h2pack(s[2 * k4][0],     s[2 * k4][1]);
            pa[1] = h2pack(s[2 * k4][2],     s[2 * k4][3]);
            pa[2] = h2pack(s[2 * k4 + 1][0], s[2 * k4 + 1][1]);
            pa[3] = h2pack(s[2 * k4 + 1][2], s[2 * k4 + 1][3]);
            #pragma unroll
            for (int np = 0; np < 4; np++) {
                uint32_t vf[4];
                ldm_x4t(vf, &Vh[cur][(16 * k4 + vrow) * HSK + 16 * np + vcol8]);
                mma_f16(o[2 * np],     pa, vf[0], vf[1]);
                mma_f16(o[2 * np + 1], pa, vf[2], vf[3]);
            }
        }
    }

    // --- epilogue ---
    l0 += __shfl_xor_sync(0xffffffffu, l0, 1);
    l0 += __shfl_xor_sync(0xffffffffu, l0, 2);
    l1 += __shfl_xor_sync(0xffffffffu, l1, 1);
    l1 += __shfl_xor_sync(0xffffffffu, l1, 2);

    if (nch == 1) {
        float* Og = Out + ((size_t)b * TLEN + (size_t)qb * 64) * HD;
        float i0 = 1.f / l0, i1 = 1.f / l1;
        #pragma unroll
        for (int nt = 0; nt < 8; nt++) {
            int c0 = 8 * nt + 2 * qi;
            *(float2*)&Og[(size_t)qr * HD + c0] =
                make_float2(o[nt][0] * i0, o[nt][1] * i0);
            *(float2*)&Og[(size_t)(qr + 8) * HD + c0] =
                make_float2(o[nt][2] * i1, o[nt][3] * i1);
        }
    } else {
        const size_t pi = ((size_t)(b * 64 + qb) * MAXNCH + chunk);
        __half* Po = g_Ph + pi * 64 * 64;
        #pragma unroll
        for (int nt = 0; nt < 8; nt++) {
            int c0 = 8 * nt + 2 * qi;
            *(__half2*)&Po[(size_t)qr * 64 + c0] =
                __floats2half2_rn(o[nt][0], o[nt][1]);
            *(__half2*)&Po[(size_t)(qr + 8) * 64 + c0] =
                __floats2half2_rn(o[nt][2], o[nt][3]);
        }
        if (qi == 0) {
            g_Pm[pi * 64 + qr]     = m0;
            g_Pl[pi * 64 + qr]     = l0;
            g_Pm[pi * 64 + qr + 8] = m1;
            g_Pl[pi * 64 + qr + 8] = l1;
        }
    }
}

// ---------------------------------------------------------------------------
// Combine fp16 partials for qb >= CH. Grid (48, NB, 4): CTA = 16 rows of one
// q-tile; 256 thr = 16 rows x 16 col-groups of 4. Chunk loop statically
// unrolled over MAXNCH with predication -> all loads issue independently.
// ---------------------------------------------------------------------------
__global__ __launch_bounds__(256) void combine_kernel(float* __restrict__ Out)
{
    const int qb   = CH + (int)blockIdx.x;    // 16..63
    const int b    = blockIdx.y;
    const int rg   = blockIdx.z;              // 0..3: row group of 16
    const int nch  = qb / CH + 1;             // 2..4
    const int tid  = threadIdx.x;
    const int row  = rg * 16 + (tid >> 4);    // 0..63
    const int c0   = (tid & 15) * 4;          // 0..60
    const size_t qt = (size_t)(b * 64 + qb);

    float mv[MAXNCH], lv[MAXNCH];
    uint2 pv[MAXNCH];
    #pragma unroll
    for (int c = 0; c < MAXNCH; c++) {
        bool on = (c < nch);
        size_t pc = (qt * MAXNCH + c) * 64;
        mv[c] = on ? g_Pm[pc + row] : -1e30f;
        lv[c] = on ? g_Pl[pc + row] : 0.f;
        pv[c] = on ? *(const uint2*)(g_Ph + (pc + row) * 64 + c0)
                   : make_uint2(0u, 0u);
    }

    float mmax = -1e30f;
    #pragma unroll
    for (int c = 0; c < MAXNCH; c++) mmax = fmaxf(mmax, mv[c]);
    float denom = 0.f;
    float w[MAXNCH];
    #pragma unroll
    for (int c = 0; c < MAXNCH; c++) {
        w[c] = (c < nch) ? ex2f(mv[c] - mmax) : 0.f;
        denom += w[c] * lv[c];
    }
    const float inv = 1.f / denom;

    float acc0 = 0.f, acc1 = 0.f, acc2 = 0.f, acc3 = 0.f;
    #pragma unroll
    for (int c = 0; c < MAXNCH; c++) {
        float2 f0 = __half22float2(*(const __half2*)&pv[c].x);
        float2 f1 = __half22float2(*(const __half2*)&pv[c].y);
        acc0 += w[c] * f0.x;
        acc1 += w[c] * f0.y;
        acc2 += w[c] * f1.x;
        acc3 += w[c] * f1.y;
    }

    *(float4*)(Out + ((size_t)b * TLEN + (size_t)qb * 64 + row) * HD + c0) =
        make_float4(acc0 * inv, acc1 * inv, acc2 * inv, acc3 * inv);
}

// ---------------------------------------------------------------------------
extern "C" void kernel_launch(void* const* d_in, const int* in_sizes, int n_in,
                              void* d_out, int out_size)
{
    const float* x  = (const float*)d_in[0];
    const float* Wq = (const float*)d_in[1];
    const float* Wk = (const float*)d_in[2];
    const float* Wv = (const float*)d_in[3];
    float* out = (float*)d_out;

    const int smem_qkv  = 64 * XFS * (int)sizeof(float)
                        + (64 * XSK + 128 * WSK) * (int)sizeof(__half); // 102400
    const int smem_attn = 4 * 64 * HSK * (int)sizeof(__half);           // 36864

    cudaFuncSetAttribute(qkv_kernel,
        cudaFuncAttributeMaxDynamicSharedMemorySize, smem_qkv);
    cudaFuncSetAttribute(attn_kernel,
        cudaFuncAttributeMaxDynamicSharedMemorySize, smem_attn);

    cvtw_kernel<<<24, 256>>>(Wq, Wk, Wv);
    qkv_kernel<<<BT / 64, 256, smem_qkv>>>(x);
    attn_kernel<<<dim3(160, NB), 128, smem_attn>>>(out);
    combine_kernel<<<dim3(64 - CH, NB, 4), 256>>>(out);
}